// round 14
// baseline (speedup 1.0000x reference)
#include <cuda_runtime.h>
#include <cuda_fp16.h>
#include <cstdint>

// ======================= problem constants =======================
static constexpr int MUL  = 192;
static constexpr int FEAT = 1728;

static constexpr int NCTA = 148;
static constexpr int C0 = 16, C1 = 49;        // C2 = 148-16-49 = 83

static constexpr int NTHR   = 512;
static constexpr int TILE_M = 128;

// SMEM layout (dynamic):
//  [0, 73728)         W   : 192 rows(n) x 384B fp16, swizzle (ci ^ (n&7)) on 16B chunks
//  [73728, +6*16384)  F16 : 6 bufs (stage = 3*(t&1)+c), 128 rows x 128B fp16, ldsm swizzle
static constexpr int SM_W     = 0;
static constexpr int W_ONE    = 73728;
static constexpr int SM_F16   = W_ONE;                     // 73728
static constexpr int F16_BUF  = 16384;
static constexpr int SMEM_TOTAL = SM_F16 + 6 * F16_BUF;    // 172032

// Folded weights, fp16, layout [k][o][m]  (B operand: n rows, k cols)
__device__ __align__(16) __half g_W[3 * MUL * MUL];

// ======================= prep: fold LoRA -> fp16 =======================
__global__ void prep_weights_kernel(const float* __restrict__ Wb,
                                    const float* __restrict__ WA,
                                    const float* __restrict__ WB) {
    int idx = blockIdx.x * blockDim.x + threadIdx.x;
    if (idx >= 3 * MUL * MUL) return;
    int k   = idx / (MUL * MUL);
    int rem = idx - k * (MUL * MUL);
    int o   = rem / MUL;            // output channel (n)
    int m   = rem - o * MUL;        // input channel  (k of GEMM)

    const float pw_base = rsqrtf(192.0f);
    const float pw_B    = rsqrtf(8.0f);

    float acc = 0.0f;
#pragma unroll
    for (int r = 0; r < 8; r++)
        acc += WA[(k * MUL + m) * 8 + r] * WB[(k * 8 + r) * MUL + o];
    float w = pw_base * Wb[(k * MUL + m) * MUL + o] + 2.0f * pw_base * pw_B * acc;

    g_W[idx] = __float2half_rn(w);   // [k][o][m]
}

// ======================= device helpers =======================
__device__ __forceinline__ uint32_t smem_to_u32(const void* p) {
    uint32_t a;
    asm("{ .reg .u64 t; cvta.to.shared.u64 t, %1; cvt.u32.u64 %0, t; }"
        : "=r"(a) : "l"(p));
    return a;
}

__device__ __forceinline__ unsigned row_to_node(unsigned g, int d) {
    if (d == 1) return g;
    if (d == 3) return __umulhi(g, 0xAAAAAAABu) >> 1;
    return __umulhi(g, 0xCCCCCCCDu) >> 2;   // d == 5
}

__device__ __forceinline__ void ldsm4(uint32_t& r0, uint32_t& r1,
                                      uint32_t& r2, uint32_t& r3, uint32_t addr) {
    asm volatile("ldmatrix.sync.aligned.m8n8.x4.shared.b16 {%0,%1,%2,%3}, [%4];"
                 : "=r"(r0), "=r"(r1), "=r"(r2), "=r"(r3) : "r"(addr));
}

__device__ __forceinline__ void mma16816(float c[4], const uint32_t a[4],
                                         const uint32_t b[2]) {
    asm volatile("mma.sync.aligned.m16n8k16.row.col.f32.f16.f16.f32 "
                 "{%0,%1,%2,%3}, {%4,%5,%6,%7}, {%8,%9}, {%0,%1,%2,%3};"
                 : "+f"(c[0]), "+f"(c[1]), "+f"(c[2]), "+f"(c[3])
                 : "r"(a[0]), "r"(a[1]), "r"(a[2]), "r"(a[3]),
                   "r"(b[0]), "r"(b[1]));
}

__device__ __forceinline__ uint32_t cvt_h2(float a, float b) {
    __half2 h = __floats2half2_rn(a, b);
    return *reinterpret_cast<uint32_t*>(&h);
}

// named barriers (count 512): full[s] = 1+s (s=0..5), empty[s] = 7+s
#define BAR_SYNC(id)   asm volatile("bar.sync %0, 512;"   :: "r"(id) : "memory")
#define BAR_ARRIVE(id) asm volatile("bar.arrive %0, 512;" :: "r"(id) : "memory")

// ======================= main kernel =======================
extern "C" __global__ void __launch_bounds__(NTHR, 1)
lora_linear_main(const float* __restrict__ x, float* __restrict__ out, int n) {
    extern __shared__ char smem[];
    const uint32_t sb  = smem_to_u32(smem);
    const int tid  = threadIdx.x;
    const int lane = tid & 31;
    const int wid  = tid >> 5;

    // ---- CTA -> (irrep, tile range) ----
    int b = blockIdx.x;
    int k, idx, nC;
    if (b < C0)            { k = 0; idx = b;            nC = C0; }
    else if (b < C0 + C1)  { k = 1; idx = b - C0;       nC = C1; }
    else                   { k = 2; idx = b - C0 - C1;  nC = NCTA - C0 - C1; }
    const int d      = (k == 0) ? 1 : (k == 1) ? 3 : 5;
    const int segoff = (k == 0) ? 0 : (k == 1) ? 192 : 768;
    const int rows   = n * d;
    const int T      = (rows + TILE_M - 1) / TILE_M;
    const int t0 = (int)(((long long)idx * T) / nC);
    const int t1 = (int)(((long long)(idx + 1) * T) / nC);

    // ---- copy W into smem, XOR row-swizzle (16B chunk ci ^= (n & 7)) ----
    {
        const float4* gw = reinterpret_cast<const float4*>(g_W + (size_t)k * MUL * MUL);
        for (int i = tid; i < W_ONE / 16; i += NTHR) {   // 4608 chunks
            int nrow = i / 24;
            int ci   = i - nrow * 24;
            int dst  = nrow * 384 + (ci ^ (nrow & 7)) * 16;
            *reinterpret_cast<float4*>(smem + SM_W + dst) = gw[i];
        }
    }
    __syncthreads();

    if (wid < 4) {
        // ================= PRODUCER: 4 warps (128 threads) =================
        // Thread owns 16 (row, ci) slots of the 128x64 chunk: r = (ptid>>4)+8q, ci = ptid&15
        const int ptid  = tid;             // 0..127
        const int ci    = ptid & 15;
        const int rbase = ptid >> 4;       // 0..7

        uint32_t f16off[16];
#pragma unroll
        for (int q = 0; q < 16; q++) {
            int r = rbase + 8 * q;
            f16off[q] = (uint32_t)(r * 128 + (((ci >> 1) ^ (r & 7)) << 4) +
                                   ((ci & 1) << 3));
        }

        const float* pb[16];
        bool pok[16];
        auto comp_base = [&](int t) {
#pragma unroll
            for (int q = 0; q < 16; q++) {
                int r    = rbase + 8 * q;
                int grow = t * TILE_M + r;
                pok[q] = grow < rows;
                unsigned gr   = (unsigned)(pok[q] ? grow : 0);
                unsigned node = row_to_node(gr, d);
                unsigned sub  = gr - node * (unsigned)d;
                pb[q] = x + (size_t)node * FEAT + segoff + sub * 192 + ci * 4;
            }
        };

        for (int t = t0; t < t1; ++t) {
            comp_base(t);
#pragma unroll
            for (int c = 0; c < 3; ++c) {
                const int s = 3 * (t & 1) + c;
                if (t >= t0 + 2) BAR_SYNC(7 + s);           // f16 buf s free

                // LDG fp32 (16 independent loads, MLP 16)
                float4 v[16];
#pragma unroll
                for (int q = 0; q < 16; q++) {
                    float4 vv = make_float4(0.f, 0.f, 0.f, 0.f);
                    if (pok[q]) vv = *reinterpret_cast<const float4*>(pb[q] + c * 64);
                    v[q] = vv;
                }
                // cvt + STS fp16
                const uint32_t sH = sb + (uint32_t)(SM_F16 + s * F16_BUF);
#pragma unroll
                for (int q = 0; q < 16; q++) {
                    uint32_t u0 = cvt_h2(v[q].x, v[q].y);
                    uint32_t u1 = cvt_h2(v[q].z, v[q].w);
                    asm volatile("st.shared.v2.b32 [%0], {%1,%2};"
                                 :: "r"(sH + f16off[q]), "r"(u0), "r"(u1) : "memory");
                }
                BAR_ARRIVE(1 + s);                          // f16 buf s full
            }
        }
    } else {
        // ================= CONSUMER: 12 warps, 4m x 3n =================
        const int cw  = wid - 4;          // 0..11
        const int wm4 = cw & 3;           // 32-row group of 128
        const int wn3 = cw >> 2;          // 64-col group of 192
        const uint32_t Wm = sb + (uint32_t)SM_W;

        const int arow0 = 32 * wm4 + (lane & 7) + 8 * ((lane >> 3) & 1);
        const int hl    = lane >> 4;
        const int bsel  = (lane >> 3) & 1;

        float acc[2][8][4];
        uint32_t bfr[2][8][2];

        auto load_b = [&](uint32_t bf[8][2], int c, int ki) {
            const int cib = c * 8 + ki * 2 + bsel;
#pragma unroll
            for (int nb2 = 0; nb2 < 4; nb2++) {
                int nrow = 64 * wn3 + nb2 * 16 + 8 * hl + (lane & 7);
                uint32_t addr = Wm + (uint32_t)(nrow * 384 + ((cib ^ (nrow & 7)) << 4));
                ldsm4(bf[2 * nb2][0], bf[2 * nb2][1],
                      bf[2 * nb2 + 1][0], bf[2 * nb2 + 1][1], addr);
            }
        };

        auto ldsmA = [&](uint32_t a[4], uint32_t sA, int ki, int mi) {
            int rA  = arow0 + 16 * mi;
            int cia = ki * 2 + hl;
            uint32_t addr = sA + (uint32_t)(rA * 128 + ((cia ^ (rA & 7)) << 4));
            ldsm4(a[0], a[1], a[2], a[3], addr);
        };

        for (int t = t0; t < t1; ++t) {
#pragma unroll
            for (int c = 0; c < 3; ++c) {
                const int s = 3 * (t & 1) + c;
                const uint32_t sA = sb + (uint32_t)(SM_F16 + s * F16_BUF);

                load_b(bfr[0], c, 0);            // W static: overlaps barrier wait
                BAR_SYNC(1 + s);                 // f16 buf s full

                if (c == 0) {
#pragma unroll
                    for (int mi = 0; mi < 2; mi++)
#pragma unroll
                        for (int nb = 0; nb < 8; nb++)
#pragma unroll
                            for (int j = 0; j < 4; j++) acc[mi][nb][j] = 0.0f;
                }

                // software-pipelined A (ping-pong) + B (ping-pong)
                uint32_t a[2][4];
                ldsmA(a[0], sA, 0, 0);
#pragma unroll
                for (int ki = 0; ki < 4; ki++) {
                    if (ki < 3) load_b(bfr[(ki + 1) & 1], c, ki + 1);
#pragma unroll
                    for (int mi = 0; mi < 2; mi++) {
                        const int p = 2 * ki + mi;
                        if (p < 7) {
                            const int nk = (mi == 0) ? ki : ki + 1;
                            const int nm = (mi == 0) ? 1 : 0;
                            ldsmA(a[(p + 1) & 1], sA, nk, nm);
                        }
#pragma unroll
                        for (int nb = 0; nb < 8; nb++)
                            mma16816(acc[mi][nb], a[p & 1], bfr[ki & 1][nb]);
                    }
                }

                BAR_ARRIVE(7 + s);               // f16 buf s free

                if (c == 2) {
                    const int g  = lane >> 2;
                    const int t4 = lane & 3;
#pragma unroll
                    for (int mi = 0; mi < 2; mi++) {
#pragma unroll
                        for (int half = 0; half < 2; half++) {
                            int r    = 32 * wm4 + 16 * mi + 8 * half + g;
                            int grow = t * TILE_M + r;
                            if (grow < rows) {
                                unsigned gr   = (unsigned)grow;
                                unsigned node = row_to_node(gr, d);
                                unsigned sub  = gr - node * (unsigned)d;
                                float* po = out + (size_t)node * FEAT + segoff +
                                            sub * 192 + 64 * wn3 + t4 * 2;
#pragma unroll
                                for (int nb = 0; nb < 8; nb++) {
                                    float2 v = make_float2(acc[mi][nb][2 * half],
                                                           acc[mi][nb][2 * half + 1]);
                                    *reinterpret_cast<float2*>(po + nb * 8) = v;
                                }
                            }
                        }
                    }
                }
            }
        }
    }
}

// ======================= launch =======================
extern "C" void kernel_launch(void* const* d_in, const int* in_sizes, int n_in,
                              void* d_out, int out_size) {
    const float* x  = (const float*)d_in[0];
    const float* Wb = (const float*)d_in[1];
    const float* WA = (const float*)d_in[2];
    const float* WB = (const float*)d_in[3];
    float* out = (float*)d_out;
    int n = in_sizes[0] / FEAT;

    static bool attr_set = false;
    if (!attr_set) {
        cudaFuncSetAttribute(lora_linear_main,
                             cudaFuncAttributeMaxDynamicSharedMemorySize, SMEM_TOTAL);
        attr_set = true;
    }

    prep_weights_kernel<<<(3 * MUL * MUL + 255) / 256, 256>>>(Wb, WA, WB);
    lora_linear_main<<<NCTA, NTHR, SMEM_TOTAL>>>(x, out, n);
}

// round 15
// speedup vs baseline: 1.1099x; 1.1099x over previous
#include <cuda_runtime.h>
#include <cuda_fp16.h>
#include <cstdint>

// ======================= problem constants =======================
static constexpr int MUL  = 192;
static constexpr int FEAT = 1728;

static constexpr int NCTA = 148;
static constexpr int C0 = 16, C1 = 49;        // C2 = 148-16-49 = 83

static constexpr int NTHR   = 512;
static constexpr int TILE_M = 128;

// SMEM layout (dynamic):
//  [0, 73728)         W   : 192 rows(n) x 384B fp16, swizzle (ci ^ (n&7)) on 16B chunks
//  [73728, +2*32768)  F32 : 2 stages (stage = cc&1), 128 rows x 256B fp32
//  [139264, +4*16384) F16 : 4 bufs  (buf = cc&3),    128 rows x 128B fp16, ldsm swizzle
static constexpr int SM_W     = 0;
static constexpr int W_ONE    = 73728;
static constexpr int SM_F32   = W_ONE;                     // 73728
static constexpr int F32_STG  = 32768;
static constexpr int SM_F16   = SM_F32 + 2 * F32_STG;      // 139264
static constexpr int F16_BUF  = 16384;
static constexpr int SMEM_TOTAL = SM_F16 + 4 * F16_BUF;    // 204800

// Folded weights, fp16, layout [k][o][m]  (B operand: n rows, k cols)
__device__ __align__(16) __half g_W[3 * MUL * MUL];

// ======================= prep: fold LoRA -> fp16 =======================
__global__ void prep_weights_kernel(const float* __restrict__ Wb,
                                    const float* __restrict__ WA,
                                    const float* __restrict__ WB) {
    int idx = blockIdx.x * blockDim.x + threadIdx.x;
    if (idx >= 3 * MUL * MUL) return;
    int k   = idx / (MUL * MUL);
    int rem = idx - k * (MUL * MUL);
    int o   = rem / MUL;            // output channel (n)
    int m   = rem - o * MUL;        // input channel  (k of GEMM)

    const float pw_base = rsqrtf(192.0f);
    const float pw_B    = rsqrtf(8.0f);

    float acc = 0.0f;
#pragma unroll
    for (int r = 0; r < 8; r++)
        acc += WA[(k * MUL + m) * 8 + r] * WB[(k * 8 + r) * MUL + o];
    float w = pw_base * Wb[(k * MUL + m) * MUL + o] + 2.0f * pw_base * pw_B * acc;

    g_W[idx] = __float2half_rn(w);   // [k][o][m]
}

// ======================= device helpers =======================
__device__ __forceinline__ uint32_t smem_to_u32(const void* p) {
    uint32_t a;
    asm("{ .reg .u64 t; cvta.to.shared.u64 t, %1; cvt.u32.u64 %0, t; }"
        : "=r"(a) : "l"(p));
    return a;
}

__device__ __forceinline__ unsigned row_to_node(unsigned g, int d) {
    if (d == 1) return g;
    if (d == 3) return __umulhi(g, 0xAAAAAAABu) >> 1;
    return __umulhi(g, 0xCCCCCCCDu) >> 2;   // d == 5
}

__device__ __forceinline__ void ldsm4(uint32_t& r0, uint32_t& r1,
                                      uint32_t& r2, uint32_t& r3, uint32_t addr) {
    asm volatile("ldmatrix.sync.aligned.m8n8.x4.shared.b16 {%0,%1,%2,%3}, [%4];"
                 : "=r"(r0), "=r"(r1), "=r"(r2), "=r"(r3) : "r"(addr));
}

__device__ __forceinline__ void mma16816(float c[4], const uint32_t a[4],
                                         const uint32_t b[2]) {
    asm volatile("mma.sync.aligned.m16n8k16.row.col.f32.f16.f16.f32 "
                 "{%0,%1,%2,%3}, {%4,%5,%6,%7}, {%8,%9}, {%0,%1,%2,%3};"
                 : "+f"(c[0]), "+f"(c[1]), "+f"(c[2]), "+f"(c[3])
                 : "r"(a[0]), "r"(a[1]), "r"(a[2]), "r"(a[3]),
                   "r"(b[0]), "r"(b[1]));
}

__device__ __forceinline__ uint32_t cvt_h2(float a, float b) {
    __half2 h = __floats2half2_rn(a, b);
    return *reinterpret_cast<uint32_t*>(&h);
}

// named barriers (count 512): full[s] = 1+s (s=0..3), empty[s] = 5+s
#define BAR_SYNC(id)   asm volatile("bar.sync %0, 512;"   :: "r"(id) : "memory")
#define BAR_ARRIVE(id) asm volatile("bar.arrive %0, 512;" :: "r"(id) : "memory")

// ======================= main kernel =======================
extern "C" __global__ void __launch_bounds__(NTHR, 1)
lora_linear_main(const float* __restrict__ x, float* __restrict__ out, int n) {
    extern __shared__ char smem[];
    const uint32_t sb  = smem_to_u32(smem);
    const int tid  = threadIdx.x;
    const int lane = tid & 31;
    const int wid  = tid >> 5;

    // ---- CTA -> (irrep, tile range) ----
    int b = blockIdx.x;
    int k, idx, nC;
    if (b < C0)            { k = 0; idx = b;            nC = C0; }
    else if (b < C0 + C1)  { k = 1; idx = b - C0;       nC = C1; }
    else                   { k = 2; idx = b - C0 - C1;  nC = NCTA - C0 - C1; }
    const int d      = (k == 0) ? 1 : (k == 1) ? 3 : 5;
    const int segoff = (k == 0) ? 0 : (k == 1) ? 192 : 768;
    const int rows   = n * d;
    const int T      = (rows + TILE_M - 1) / TILE_M;
    const int t0 = (int)(((long long)idx * T) / nC);
    const int t1 = (int)(((long long)(idx + 1) * T) / nC);

    // ---- copy W into smem, XOR row-swizzle (16B chunk ci ^= (n & 7)) ----
    {
        const float4* gw = reinterpret_cast<const float4*>(g_W + (size_t)k * MUL * MUL);
        for (int i = tid; i < W_ONE / 16; i += NTHR) {   // 4608 chunks
            int nrow = i / 24;
            int ci   = i - nrow * 24;
            int dst  = nrow * 384 + (ci ^ (nrow & 7)) * 16;
            *reinterpret_cast<float4*>(smem + SM_W + dst) = gw[i];
        }
    }
    __syncthreads();

    if (wid < 4) {
        // ================= PRODUCER: 4 warps (128 threads) =================
        const int ptid  = tid;             // 0..127
        const int ci    = ptid & 15;
        const int rbase = ptid >> 4;       // 0..7

        uint32_t f32off[16];
        uint32_t f16off[16];
#pragma unroll
        for (int q = 0; q < 16; q++) {
            int r = rbase + 8 * q;
            f32off[q] = (uint32_t)(r * 256 + ((ci ^ (2 * (r & 7))) & 15) * 16);
            f16off[q] = (uint32_t)(r * 128 + (((ci >> 1) ^ (r & 7)) << 4) +
                                   ((ci & 1) << 3));
        }

        const float* pb[16];
        bool pok[16];
        int cur_tile = -999;
        auto comp_base = [&](int t) {
#pragma unroll
            for (int q = 0; q < 16; q++) {
                int r    = rbase + 8 * q;
                int grow = t * TILE_M + r;
                pok[q] = grow < rows;
                unsigned gr   = (unsigned)(pok[q] ? grow : 0);
                unsigned node = row_to_node(gr, d);
                unsigned sub  = gr - node * (unsigned)d;
                pb[q] = x + (size_t)node * FEAT + segoff + sub * 192 + ci * 4;
            }
        };

        int iss32 = 0;                       // f32 stage of next issue
        auto issue_cps = [&](int t, int c) {
            if (t < t1) {
                if (t != cur_tile) { comp_base(t); cur_tile = t; }
                const uint32_t sF = sb + (uint32_t)(SM_F32 + iss32 * F32_STG);
#pragma unroll
                for (int q = 0; q < 16; q++) {
                    const float* src = pb[q] + c * 64;
                    int sz = pok[q] ? 16 : 0;
                    asm volatile("cp.async.cg.shared.global [%0], [%1], 16, %2;"
                                 :: "r"(sF + f32off[q]), "l"(src), "r"(sz) : "memory");
                }
            }
            asm volatile("cp.async.commit_group;" ::: "memory");
            iss32 ^= 1;
        };

        // prologue: 2 chunks in flight
        issue_cps(t0, 0);
        issue_cps(t0, 1);

        int s32 = 0;       // f32 stage to consume
        int s16 = 0;       // f16 buf to fill
        for (int t = t0; t < t1; ++t) {
#pragma unroll
            for (int c = 0; c < 3; ++c) {
                asm volatile("cp.async.wait_group 1;" ::: "memory");  // f32 stage s32 ready
                const int cc = 3 * (t - t0) + c;
                if (cc >= 4) BAR_SYNC(5 + s16);                        // f16 buf s16 free

                const uint32_t sFo = (uint32_t)(SM_F32 + s32 * F32_STG);
                const uint32_t sH  = sb + (uint32_t)(SM_F16 + s16 * F16_BUF);
#pragma unroll
                for (int q = 0; q < 16; q++) {
                    float4 v = *reinterpret_cast<const float4*>(smem + sFo + f32off[q]);
                    uint32_t u0 = cvt_h2(v.x, v.y);
                    uint32_t u1 = cvt_h2(v.z, v.w);
                    asm volatile("st.shared.v2.b32 [%0], {%1,%2};"
                                 :: "r"(sH + f16off[q]), "r"(u0), "r"(u1) : "memory");
                }
                BAR_ARRIVE(1 + s16);                                   // f16 buf s16 full

                // issue chunk cc+2 (c+2 pattern resolved at compile time per c)
                if (c == 0)      issue_cps(t, 2);
                else if (c == 1) issue_cps(t + 1, 0);
                else             issue_cps(t + 1, 1);

                s32 ^= 1;
                s16 = (s16 + 1) & 3;
            }
        }
    } else {
        // ================= CONSUMER: 12 warps, 4m x 3n =================
        const int cw  = wid - 4;          // 0..11
        const int wm4 = cw & 3;           // 32-row group of 128
        const int wn3 = cw >> 2;          // 64-col group of 192
        const uint32_t Wm = sb + (uint32_t)SM_W;

        const int arow0 = 32 * wm4 + (lane & 7) + 8 * ((lane >> 3) & 1);
        const int hl    = lane >> 4;
        const int bsel  = (lane >> 3) & 1;

        float acc[2][8][4];
        uint32_t bfr[2][8][2];

        auto load_b = [&](uint32_t bf[8][2], int c, int ki) {
            const int cib = c * 8 + ki * 2 + bsel;
#pragma unroll
            for (int nb2 = 0; nb2 < 4; nb2++) {
                int nrow = 64 * wn3 + nb2 * 16 + 8 * hl + (lane & 7);
                uint32_t addr = Wm + (uint32_t)(nrow * 384 + ((cib ^ (nrow & 7)) << 4));
                ldsm4(bf[2 * nb2][0], bf[2 * nb2][1],
                      bf[2 * nb2 + 1][0], bf[2 * nb2 + 1][1], addr);
            }
        };

        auto ldsmA = [&](uint32_t a[4], uint32_t sA, int ki, int mi) {
            int rA  = arow0 + 16 * mi;
            int cia = ki * 2 + hl;
            uint32_t addr = sA + (uint32_t)(rA * 128 + ((cia ^ (rA & 7)) << 4));
            ldsm4(a[0], a[1], a[2], a[3], addr);
        };

        int s16 = 0;
        for (int t = t0; t < t1; ++t) {
#pragma unroll
            for (int c = 0; c < 3; ++c) {
                const uint32_t sA = sb + (uint32_t)(SM_F16 + s16 * F16_BUF);

                load_b(bfr[0], c, 0);            // W static: overlaps barrier wait
                BAR_SYNC(1 + s16);               // f16 buf s16 full

                if (c == 0) {
#pragma unroll
                    for (int mi = 0; mi < 2; mi++)
#pragma unroll
                        for (int nb = 0; nb < 8; nb++)
#pragma unroll
                            for (int j = 0; j < 4; j++) acc[mi][nb][j] = 0.0f;
                }

                // software-pipelined A (ping-pong) + B (ping-pong)
                uint32_t a[2][4];
                ldsmA(a[0], sA, 0, 0);
#pragma unroll
                for (int ki = 0; ki < 4; ki++) {
                    if (ki < 3) load_b(bfr[(ki + 1) & 1], c, ki + 1);
#pragma unroll
                    for (int mi = 0; mi < 2; mi++) {
                        const int p = 2 * ki + mi;
                        if (p < 7) {
                            const int nk = (mi == 0) ? ki : ki + 1;
                            const int nm = (mi == 0) ? 1 : 0;
                            ldsmA(a[(p + 1) & 1], sA, nk, nm);
                        }
#pragma unroll
                        for (int nb = 0; nb < 8; nb++)
                            mma16816(acc[mi][nb], a[p & 1], bfr[ki & 1][nb]);
                    }
                }

                BAR_ARRIVE(5 + s16);             // f16 buf s16 free
                s16 = (s16 + 1) & 3;

                if (c == 2) {
                    const int g  = lane >> 2;
                    const int t4 = lane & 3;
#pragma unroll
                    for (int mi = 0; mi < 2; mi++) {
#pragma unroll
                        for (int half = 0; half < 2; half++) {
                            int r    = 32 * wm4 + 16 * mi + 8 * half + g;
                            int grow = t * TILE_M + r;
                            if (grow < rows) {
                                unsigned gr   = (unsigned)grow;
                                unsigned node = row_to_node(gr, d);
                                unsigned sub  = gr - node * (unsigned)d;
                                float* po = out + (size_t)node * FEAT + segoff +
                                            sub * 192 + 64 * wn3 + t4 * 2;
#pragma unroll
                                for (int nb = 0; nb < 8; nb++) {
                                    float2 v = make_float2(acc[mi][nb][2 * half],
                                                           acc[mi][nb][2 * half + 1]);
                                    *reinterpret_cast<float2*>(po + nb * 8) = v;
                                }
                            }
                        }
                    }
                }
            }
        }
    }
}

// ======================= launch =======================
extern "C" void kernel_launch(void* const* d_in, const int* in_sizes, int n_in,
                              void* d_out, int out_size) {
    const float* x  = (const float*)d_in[0];
    const float* Wb = (const float*)d_in[1];
    const float* WA = (const float*)d_in[2];
    const float* WB = (const float*)d_in[3];
    float* out = (float*)d_out;
    int n = in_sizes[0] / FEAT;

    static bool attr_set = false;
    if (!attr_set) {
        cudaFuncSetAttribute(lora_linear_main,
                             cudaFuncAttributeMaxDynamicSharedMemorySize, SMEM_TOTAL);
        attr_set = true;
    }

    prep_weights_kernel<<<(3 * MUL * MUL + 255) / 256, 256>>>(Wb, WA, WB);
    lora_linear_main<<<NCTA, NTHR, SMEM_TOTAL>>>(x, out, n);
}

// round 16
// speedup vs baseline: 1.2173x; 1.0968x over previous
#include <cuda_runtime.h>
#include <cuda_fp16.h>
#include <cstdint>

// ======================= problem constants =======================
static constexpr int MUL  = 192;
static constexpr int FEAT = 1728;

static constexpr int NCTA = 148;
static constexpr int C0 = 17, C1 = 49;        // C2 = 148-17-49 = 82 (balanced: max 23.9 tiles/CTA)

static constexpr int NTHR   = 512;
static constexpr int TILE_M = 128;

// SMEM layout (dynamic):
//  [0, 73728)            W    : 192 rows(n) x 384B fp16, swizzle (ci ^ (n&7)) on 16B chunks
//  [73728, +3*32768)     F32  : 3 stages (one per c), 128 rows x 256B fp32
//  [172032, +3*16384)    F16  : 3 bufs (one per c),   128 rows x 128B fp16, ldmatrix swizzle
static constexpr int SM_W     = 0;
static constexpr int W_ONE    = 73728;
static constexpr int SM_F32   = W_ONE;                     // 73728
static constexpr int F32_STG  = 32768;
static constexpr int SM_F16   = SM_F32 + 3 * F32_STG;      // 172032
static constexpr int F16_BUF  = 16384;
static constexpr int SMEM_TOTAL = SM_F16 + 3 * F16_BUF;    // 221184

// Folded weights, fp16, layout [k][o][m]  (B operand: n rows, k cols)
__device__ __align__(16) __half g_W[3 * MUL * MUL];

// ======================= prep: fold LoRA -> fp16 =======================
__global__ void prep_weights_kernel(const float* __restrict__ Wb,
                                    const float* __restrict__ WA,
                                    const float* __restrict__ WB) {
    int idx = blockIdx.x * blockDim.x + threadIdx.x;
    if (idx >= 3 * MUL * MUL) return;
    int k   = idx / (MUL * MUL);
    int rem = idx - k * (MUL * MUL);
    int o   = rem / MUL;            // output channel (n)
    int m   = rem - o * MUL;        // input channel  (k of GEMM)

    const float pw_base = rsqrtf(192.0f);
    const float pw_B    = rsqrtf(8.0f);

    float acc = 0.0f;
#pragma unroll
    for (int r = 0; r < 8; r++)
        acc += WA[(k * MUL + m) * 8 + r] * WB[(k * 8 + r) * MUL + o];
    float w = pw_base * Wb[(k * MUL + m) * MUL + o] + 2.0f * pw_base * pw_B * acc;

    g_W[idx] = __float2half_rn(w);   // [k][o][m]
}

// ======================= device helpers =======================
__device__ __forceinline__ uint32_t smem_to_u32(const void* p) {
    uint32_t a;
    asm("{ .reg .u64 t; cvta.to.shared.u64 t, %1; cvt.u32.u64 %0, t; }"
        : "=r"(a) : "l"(p));
    return a;
}

__device__ __forceinline__ unsigned row_to_node(unsigned g, int d) {
    if (d == 1) return g;
    if (d == 3) return __umulhi(g, 0xAAAAAAABu) >> 1;
    return __umulhi(g, 0xCCCCCCCDu) >> 2;   // d == 5
}

__device__ __forceinline__ void ldsm4(uint32_t& r0, uint32_t& r1,
                                      uint32_t& r2, uint32_t& r3, uint32_t addr) {
    asm volatile("ldmatrix.sync.aligned.m8n8.x4.shared.b16 {%0,%1,%2,%3}, [%4];"
                 : "=r"(r0), "=r"(r1), "=r"(r2), "=r"(r3) : "r"(addr));
}

__device__ __forceinline__ void mma16816(float c[4], const uint32_t a[4],
                                         const uint32_t b[2]) {
    asm volatile("mma.sync.aligned.m16n8k16.row.col.f32.f16.f16.f32 "
                 "{%0,%1,%2,%3}, {%4,%5,%6,%7}, {%8,%9}, {%0,%1,%2,%3};"
                 : "+f"(c[0]), "+f"(c[1]), "+f"(c[2]), "+f"(c[3])
                 : "r"(a[0]), "r"(a[1]), "r"(a[2]), "r"(a[3]),
                   "r"(b[0]), "r"(b[1]));
}

__device__ __forceinline__ uint32_t cvt_h2(float a, float b) {
    __half2 h = __floats2half2_rn(a, b);
    return *reinterpret_cast<uint32_t*>(&h);
}

// named barriers (count 512): full[c] = 1+c, empty[c] = 4+c
#define BAR_SYNC(id)   asm volatile("bar.sync %0, 512;"   :: "r"(id) : "memory")
#define BAR_ARRIVE(id) asm volatile("bar.arrive %0, 512;" :: "r"(id) : "memory")

// ======================= main kernel =======================
extern "C" __global__ void __launch_bounds__(NTHR, 1)
lora_linear_main(const float* __restrict__ x, float* __restrict__ out, int n) {
    extern __shared__ char smem[];
    const uint32_t sb  = smem_to_u32(smem);
    const int tid  = threadIdx.x;
    const int lane = tid & 31;
    const int wid  = tid >> 5;

    // ---- CTA -> (irrep, tile range) ----
    int b = blockIdx.x;
    int k, idx, nC;
    if (b < C0)            { k = 0; idx = b;            nC = C0; }
    else if (b < C0 + C1)  { k = 1; idx = b - C0;       nC = C1; }
    else                   { k = 2; idx = b - C0 - C1;  nC = NCTA - C0 - C1; }
    const int d      = (k == 0) ? 1 : (k == 1) ? 3 : 5;
    const int segoff = (k == 0) ? 0 : (k == 1) ? 192 : 768;
    const int rows   = n * d;
    const int T      = (rows + TILE_M - 1) / TILE_M;
    const int t0 = (int)(((long long)idx * T) / nC);
    const int t1 = (int)(((long long)(idx + 1) * T) / nC);

    // ---- copy W into smem, XOR row-swizzle (16B chunk ci ^= (n & 7)) ----
    {
        const float4* gw = reinterpret_cast<const float4*>(g_W + (size_t)k * MUL * MUL);
        for (int i = tid; i < W_ONE / 16; i += NTHR) {   // 4608 chunks
            int nrow = i / 24;
            int ci   = i - nrow * 24;
            int dst  = nrow * 384 + (ci ^ (nrow & 7)) * 16;
            *reinterpret_cast<float4*>(smem + SM_W + dst) = gw[i];
        }
    }
    __syncthreads();

    if (wid < 4) {
        // ================= PRODUCER: 4 warps (128 threads) =================
        const int ptid  = tid;             // 0..127
        const int ci    = ptid & 15;
        const int rbase = ptid >> 4;       // 0..7

        uint32_t f32off[16];
        uint32_t f16off[16];
#pragma unroll
        for (int q = 0; q < 16; q++) {
            int r = rbase + 8 * q;
            f32off[q] = (uint32_t)(r * 256 + ((ci ^ (2 * (r & 7))) & 15) * 16);
            f16off[q] = (uint32_t)(r * 128 + (((ci >> 1) ^ (r & 7)) << 4) +
                                   ((ci & 1) << 3));
        }

        const float* pb[16];
        bool pok[16];
        int cur_tile = -999;
        auto comp_base = [&](int t) {
#pragma unroll
            for (int q = 0; q < 16; q++) {
                int r    = rbase + 8 * q;
                int grow = t * TILE_M + r;
                pok[q] = grow < rows;
                unsigned gr   = (unsigned)(pok[q] ? grow : 0);
                unsigned node = row_to_node(gr, d);
                unsigned sub  = gr - node * (unsigned)d;
                pb[q] = x + (size_t)node * FEAT + segoff + sub * 192 + ci * 4;
            }
        };

        auto issue_cps = [&](int t, int c) {      // stage index == c
            if (t < t1) {
                if (t != cur_tile) { comp_base(t); cur_tile = t; }
                const uint32_t sF = sb + (uint32_t)(SM_F32 + c * F32_STG);
#pragma unroll
                for (int q = 0; q < 16; q++) {
                    const float* src = pb[q] + c * 64;
                    int sz = pok[q] ? 16 : 0;
                    asm volatile("cp.async.cg.shared.global [%0], [%1], 16, %2;"
                                 :: "r"(sF + f32off[q]), "l"(src), "r"(sz) : "memory");
                }
            }
            asm volatile("cp.async.commit_group;" ::: "memory");
        };

        issue_cps(t0, 0); issue_cps(t0, 1); issue_cps(t0, 2);

        for (int t = t0; t < t1; ++t) {
#pragma unroll
            for (int c = 0; c < 3; ++c) {
                asm volatile("cp.async.wait_group 2;" ::: "memory");  // f32 stage c ready
                if (t > t0) BAR_SYNC(4 + c);                          // f16 buf c free

                const uint32_t sFo = (uint32_t)(SM_F32 + c * F32_STG);
                const uint32_t sH  = sb + (uint32_t)(SM_F16 + c * F16_BUF);
#pragma unroll
                for (int q = 0; q < 16; q++) {
                    float4 v = *reinterpret_cast<const float4*>(smem + sFo + f32off[q]);
                    uint32_t u0 = cvt_h2(v.x, v.y);
                    uint32_t u1 = cvt_h2(v.z, v.w);
                    asm volatile("st.shared.v2.b32 [%0], {%1,%2};"
                                 :: "r"(sH + f16off[q]), "r"(u0), "r"(u1) : "memory");
                }
                BAR_ARRIVE(1 + c);                                    // f16 buf c full
                issue_cps(t + 1, c);                                  // refill f32 stage c
            }
        }
    } else {
        // ================= CONSUMER: 12 warps, 4m x 3n =================
        const int cw  = wid - 4;          // 0..11
        const int wm4 = cw & 3;           // 32-row group of 128
        const int wn3 = cw >> 2;          // 64-col group of 192
        const uint32_t Wm = sb + (uint32_t)SM_W;

        // per-thread constant address components
        const int arow0 = 32 * wm4 + (lane & 7) + 8 * ((lane >> 3) & 1);  // A row, mi=0
        const int hl    = lane >> 4;
        const int bsel  = (lane >> 3) & 1;

        float acc[2][8][4];
        uint32_t bfr[2][8][2];

        // B-fragment loader for one 16-k slice (8 nb of this warp's 64 cols)
        auto load_b = [&](uint32_t bf[8][2], int c, int ki) {
            const int cib = c * 8 + ki * 2 + bsel;
#pragma unroll
            for (int nb2 = 0; nb2 < 4; nb2++) {
                int nrow = 64 * wn3 + nb2 * 16 + 8 * hl + (lane & 7);
                uint32_t addr = Wm + (uint32_t)(nrow * 384 + ((cib ^ (nrow & 7)) << 4));
                ldsm4(bf[2 * nb2][0], bf[2 * nb2][1],
                      bf[2 * nb2 + 1][0], bf[2 * nb2 + 1][1], addr);
            }
        };

        auto ldsmA = [&](uint32_t a[4], uint32_t sA, int ki, int mi) {
            int rA  = arow0 + 16 * mi;
            int cia = ki * 2 + hl;
            uint32_t addr = sA + (uint32_t)(rA * 128 + ((cia ^ (rA & 7)) << 4));
            ldsm4(a[0], a[1], a[2], a[3], addr);
        };

        for (int t = t0; t < t1; ++t) {
#pragma unroll
            for (int c = 0; c < 3; ++c) {
                const uint32_t sA = sb + (uint32_t)(SM_F16 + c * F16_BUF);

                load_b(bfr[0], c, 0);            // W static: overlaps barrier wait
                BAR_SYNC(1 + c);                 // f16 buf c full

                if (c == 0) {
#pragma unroll
                    for (int mi = 0; mi < 2; mi++)
#pragma unroll
                        for (int nb = 0; nb < 8; nb++)
#pragma unroll
                            for (int j = 0; j < 4; j++) acc[mi][nb][j] = 0.0f;
                }

                // software-pipelined A (ping-pong) + B (ping-pong)
                uint32_t a[2][4];
                ldsmA(a[0], sA, 0, 0);
#pragma unroll
                for (int ki = 0; ki < 4; ki++) {
                    if (ki < 3) load_b(bfr[(ki + 1) & 1], c, ki + 1);
#pragma unroll
                    for (int mi = 0; mi < 2; mi++) {
                        const int p = 2 * ki + mi;
                        if (p < 7) {
                            const int nk = (mi == 0) ? ki : ki + 1;
                            const int nm = (mi == 0) ? 1 : 0;
                            ldsmA(a[(p + 1) & 1], sA, nk, nm);
                        }
#pragma unroll
                        for (int nb = 0; nb < 8; nb++)
                            mma16816(acc[mi][nb], a[p & 1], bfr[ki & 1][nb]);
                    }
                }

                BAR_ARRIVE(4 + c);               // f16 buf c free

                if (c == 2) {
                    const int g  = lane >> 2;
                    const int t4 = lane & 3;
#pragma unroll
                    for (int mi = 0; mi < 2; mi++) {
#pragma unroll
                        for (int half = 0; half < 2; half++) {
                            int r    = 32 * wm4 + 16 * mi + 8 * half + g;
                            int grow = t * TILE_M + r;
                            if (grow < rows) {
                                unsigned gr   = (unsigned)grow;
                                unsigned node = row_to_node(gr, d);
                                unsigned sub  = gr - node * (unsigned)d;
                                float* po = out + (size_t)node * FEAT + segoff +
                                            sub * 192 + 64 * wn3 + t4 * 2;
#pragma unroll
                                for (int nb = 0; nb < 8; nb++) {
                                    float2 v = make_float2(acc[mi][nb][2 * half],
                                                           acc[mi][nb][2 * half + 1]);
                                    *reinterpret_cast<float2*>(po + nb * 8) = v;
                                }
                            }
                        }
                    }
                }
            }
        }
    }
}

// ======================= launch =======================
extern "C" void kernel_launch(void* const* d_in, const int* in_sizes, int n_in,
                              void* d_out, int out_size) {
    const float* x  = (const float*)d_in[0];
    const float* Wb = (const float*)d_in[1];
    const float* WA = (const float*)d_in[2];
    const float* WB = (const float*)d_in[3];
    float* out = (float*)d_out;
    int n = in_sizes[0] / FEAT;

    static bool attr_set = false;
    if (!attr_set) {
        cudaFuncSetAttribute(lora_linear_main,
                             cudaFuncAttributeMaxDynamicSharedMemorySize, SMEM_TOTAL);
        attr_set = true;
    }

    prep_weights_kernel<<<(3 * MUL * MUL + 255) / 256, 256>>>(Wb, WA, WB);
    lora_linear_main<<<NCTA, NTHR, SMEM_TOTAL>>>(x, out, n);
}